// round 10
// baseline (speedup 1.0000x reference)
#include <cuda_runtime.h>
#include <cstdint>

// Problem constants (from reference setup_inputs)
#define BATCH 128
#define CHAN  2048
#define PSZ   14
#define HW    196              // 14*14
#define NBOX  36

#define CT      32             // channels per block tile
#define TS      197            // smem row stride (197 % 32 = 5 -> conflict-free patterns proven below)
#define NTHREADS 256

// Output layout: fc [B,C] | att [B,HW,C] | bu [B,R,C]
#define OFF_ATT ((size_t)BATCH * CHAN)                          // 262144
#define OFF_BU  (OFF_ATT + (size_t)BATCH * HW * CHAN)           // 51642368

__global__ __launch_bounds__(NTHREADS)
void fused_pool_transpose_kernel(const float* __restrict__ images,
                                 const float* __restrict__ boxes,
                                 float* __restrict__ out)
{
    const int b   = blockIdx.y;
    const int c0  = blockIdx.x * CT;
    const int tid = threadIdx.x;

    __shared__ float tile[CT * TS];
    __shared__ int   bx1[NBOX], by1[NBOX], bx2[NBOX], by2[NBOX];
    __shared__ float binv[NBOX];

    // ---- Phase 0: box coords (threads 0..35) ----
    if (tid < NBOX) {
        const float* bp = boxes + ((size_t)b * NBOX + tid) * 4;
        int x1 = (int)rintf(bp[0] * (float)PSZ);
        int y1 = (int)rintf(bp[1] * (float)PSZ);
        int x2 = (int)rintf(bp[2] * (float)PSZ);
        int y2 = (int)rintf(bp[3] * (float)PSZ);
        // degenerate-box fix (matches reference exactly)
        if (x1 == x2) {
            if (x2 < PSZ)      x2 += 1;
            else if (x1 > 0)   x1 -= 1;
        }
        if (y1 == y2) {
            if (y2 < PSZ)      y2 += 1;
            else if (y1 > 0)   y1 -= 1;
        }
        bx1[tid] = x1; by1[tid] = y1; bx2[tid] = x2; by2[tid] = y2;
        binv[tid] = 1.0f / (float)((y2 - y1) * (x2 - x1));
    }

    // ---- Phase 1: coalesced tile load (scalar LDG, conflict-free STS) ----
    // Incremental (c,p) indexing: i += 256 -> c += 1, p += 60, wrap once if needed.
    {
        const float* src = images + ((size_t)b * CHAN + c0) * HW;
        int c = tid / HW;              // 0 or 1
        int p = tid - c * HW;
        #pragma unroll 5
        for (int i = tid; i < CT * HW; i += NTHREADS) {
            tile[c * TS + p] = src[i];
            p += NTHREADS - HW;        // +60
            c += 1;
            if (p >= HW) { p -= HW; c += 1; }
        }
    }
    __syncthreads();

    // ---- Phase 2: att transpose, vectorized STG.128 ----
    // lane = psub*8 + cg: lane covers channels 4*cg..4*cg+3 at position p0+psub.
    // LDS banks: (4*cg+k)*197 + p  ->  (20*cg + 5*k + p) mod 32: all 32 lanes
    // distinct per k-step.
    {
        const int wid  = tid >> 5;
        const int lane = tid & 31;
        const int psub = lane >> 3;        // 0..3
        const int cg   = lane & 7;         // 0..7 -> channels 4*cg..4*cg+3
        const float* t0 = tile + (4 * cg + 0) * TS;
        const float* t1 = tile + (4 * cg + 1) * TS;
        const float* t2 = tile + (4 * cg + 2) * TS;
        const float* t3 = tile + (4 * cg + 3) * TS;
        float* attb = out + OFF_ATT + (size_t)b * HW * CHAN + c0 + 4 * cg;
        // p0 takes values wid*4 + 32m; max generated p0 = 192 -> p <= 195, no guard needed
        for (int p0 = wid * 4; p0 < HW; p0 += 32) {
            const int p = p0 + psub;
            float4 v;
            v.x = t0[p];
            v.y = t1[p];
            v.z = t2[p];
            v.w = t3[p];
            *reinterpret_cast<float4*>(attb + (size_t)p * CHAN) = v;
        }
    }
    __syncthreads();

    // ---- Phase 3a: in-place y-prefix per (channel, x) column ----
    // Mapping: lane = channel (c = tid & 31), x warp-uniform (x = tid >> 5).
    // Banks = (5*c + 14*y + x) mod 32: 5*c covers all 32 banks -> CONFLICT-FREE
    // LDS and STS (vs. the old c=t/14 mapping which had 2-way conflicts).
    // Two passes: x = tid>>5 (0..7), then x = 8 + tid>>5 (warps 0..5).
    {
        const int c = tid & 31;
        float* tp = tile + c * TS;
        #pragma unroll
        for (int pass = 0; pass < 2; ++pass) {
            const int x = (tid >> 5) + pass * 8;
            if (x < PSZ) {
                float* col = tp + x;
                float s = col[0];
                #pragma unroll
                for (int y = 1; y < PSZ; ++y) {
                    s += col[y * PSZ];
                    col[y * PSZ] = s;
                }
            }
        }
    }
    __syncthreads();

    // ---- Phase 3b: bu box means + fc (task 36 == full-plane mean) ----
    // Warp-uniform r (t>>5), lanes = channels -> LDS stride 197 = conflict-free.
    for (int t = tid; t < 37 * 32; t += NTHREADS) {
        const int r = t >> 5;
        const int c = t & 31;
        const float* tp = tile + c * TS;
        if (r < NBOX) {
            const int x1 = bx1[r], x2 = bx2[r];
            const int y1 = by1[r], y2 = by2[r];
            const float* bot = tp + (y2 - 1) * PSZ;
            float s = 0.0f;
            if (y1 > 0) {
                const float* top = tp + (y1 - 1) * PSZ;
                for (int x = x1; x < x2; ++x) s += bot[x] - top[x];
            } else {
                for (int x = x1; x < x2; ++x) s += bot[x];
            }
            out[OFF_BU + ((size_t)b * NBOX + r) * CHAN + c0 + c] = s * binv[r];
        } else {
            // fc: total = sum of last prefix row
            const float* last = tp + (PSZ - 1) * PSZ;
            float s = 0.0f;
            #pragma unroll
            for (int x = 0; x < PSZ; ++x) s += last[x];
            out[(size_t)b * CHAN + c0 + c] = s * (1.0f / (float)HW);
        }
    }
}

extern "C" void kernel_launch(void* const* d_in, const int* in_sizes, int n_in,
                              void* d_out, int out_size)
{
    const float* images = (const float*)d_in[0];
    const float* boxes  = (const float*)d_in[1];
    float* out = (float*)d_out;

    dim3 grid(CHAN / CT, BATCH);   // (64, 128) = 8192 blocks
    fused_pool_transpose_kernel<<<grid, NTHREADS>>>(images, boxes, out);
}

// round 11
// speedup vs baseline: 1.0717x; 1.0717x over previous
#include <cuda_runtime.h>
#include <cstdint>

// Problem constants (from reference setup_inputs)
#define BATCH 128
#define CHAN  2048
#define PSZ   14
#define HW    196              // 14*14
#define NBOX  36

#define CT      32             // channels per block tile
#define TS      197            // smem row stride (197 % 32 = 5 -> conflict-free lane=c patterns)
#define NTHREADS 256

// Output layout: fc [B,C] | att [B,HW,C] | bu [B,R,C]
#define OFF_ATT ((size_t)BATCH * CHAN)                          // 262144
#define OFF_BU  (OFF_ATT + (size_t)BATCH * HW * CHAN)           // 51642368

__global__ __launch_bounds__(NTHREADS)
void fused_pool_transpose_kernel(const float* __restrict__ images,
                                 const float* __restrict__ boxes,
                                 float* __restrict__ out)
{
    const int b   = blockIdx.y;
    const int c0  = blockIdx.x * CT;
    const int tid = threadIdx.x;

    __shared__ float tile[CT * TS];
    __shared__ int   bx1[NBOX + 1], by1[NBOX + 1], bx2[NBOX + 1], by2[NBOX + 1];
    __shared__ float binv[NBOX + 1];
    __shared__ float zrow[PSZ];          // broadcast zero row for y1 == 0 boxes

    // ---- Phase 0: box coords (threads 0..36; task 36 = full plane -> fc) ----
    if (tid <= NBOX) {
        int x1, y1, x2, y2;
        if (tid < NBOX) {
            const float* bp = boxes + ((size_t)b * NBOX + tid) * 4;
            x1 = (int)rintf(bp[0] * (float)PSZ);
            y1 = (int)rintf(bp[1] * (float)PSZ);
            x2 = (int)rintf(bp[2] * (float)PSZ);
            y2 = (int)rintf(bp[3] * (float)PSZ);
            // degenerate-box fix (matches reference exactly)
            if (x1 == x2) {
                if (x2 < PSZ)      x2 += 1;
                else if (x1 > 0)   x1 -= 1;
            }
            if (y1 == y2) {
                if (y2 < PSZ)      y2 += 1;
                else if (y1 > 0)   y1 -= 1;
            }
        } else {
            x1 = 0; y1 = 0; x2 = PSZ; y2 = PSZ;   // fc as a full-plane box
        }
        bx1[tid] = x1; by1[tid] = y1; bx2[tid] = x2; by2[tid] = y2;
        binv[tid] = 1.0f / (float)((y2 - y1) * (x2 - x1));
    } else if (tid < NBOX + 1 + PSZ) {
        zrow[tid - (NBOX + 1)] = 0.0f;
    }

    // ---- Phase 1: coalesced tile load, incremental single smem offset ----
    // i = tid + 256*it -> (c,p): step +256 means p += 60, c += 1 (saddr += 257),
    // plus on wrap p -= 196, c += 1 (saddr += 1 more).
    {
        const float* src = images + ((size_t)b * CHAN + c0) * HW + tid;
        int p = tid;
        int saddr = 0;
        if (p >= HW) { p -= HW; saddr = TS; }
        saddr += p;
        #pragma unroll
        for (int it = 0; it < 24; ++it) {
            tile[saddr] = __ldcs(src);
            src += NTHREADS;
            saddr += TS + (NTHREADS - HW);        // +257
            p += NTHREADS - HW;                   // +60
            if (p >= HW) { p -= HW; saddr += 1; } // extra channel hop
        }
        // tail: i = 6144 + tid < 6272 -> tid < 128
        if (tid < CT * HW - 24 * NTHREADS) {
            tile[saddr] = __ldcs(src);
        }
    }
    __syncthreads();

    // ---- Phase 2: att transpose, vectorized STG.128 ----
    // lane = psub*8 + cg; banks (20*cg + 5*k + p) mod 32 distinct per k-step.
    {
        const int wid  = tid >> 5;
        const int lane = tid & 31;
        const int psub = lane >> 3;        // 0..3
        const int cg   = lane & 7;         // 0..7 -> channels 4*cg..4*cg+3
        const float* t0 = tile + (4 * cg + 0) * TS + psub;
        const float* t1 = tile + (4 * cg + 1) * TS + psub;
        const float* t2 = tile + (4 * cg + 2) * TS + psub;
        const float* t3 = tile + (4 * cg + 3) * TS + psub;
        float4* attb = (float4*)(out + OFF_ATT + (size_t)b * HW * CHAN
                                 + (size_t)(wid * 4 + psub) * CHAN + c0 + 4 * cg);
        #pragma unroll
        for (int m = 0; m < 7; ++m) {
            const int p0 = wid * 4 + 32 * m;
            if (p0 < HW) {
                const int p = p0 + psub;
                float4 v;
                v.x = t0[p0];
                v.y = t1[p0];
                v.z = t2[p0];
                v.w = t3[p0];
                __stcs(attb, v);
                (void)p;
            }
            attb += 32 * CHAN / 4;
        }
    }
    __syncthreads();

    // ---- Phase 3a: in-place y-prefix per (channel, x) column ----
    // lane = channel, x warp-uniform -> banks 5c+const -> conflict-free.
    // Batched loads (MLP=14) before the add chain.
    {
        const int c = tid & 31;
        float* tp = tile + c * TS;
        #pragma unroll
        for (int pass = 0; pass < 2; ++pass) {
            const int x = (tid >> 5) + pass * 8;
            if (x < PSZ) {
                float* col = tp + x;
                float v[PSZ];
                #pragma unroll
                for (int y = 0; y < PSZ; ++y) v[y] = col[y * PSZ];
                #pragma unroll
                for (int y = 1; y < PSZ; ++y) v[y] += v[y - 1];
                #pragma unroll
                for (int y = 1; y < PSZ; ++y) col[y * PSZ] = v[y];
            }
        }
    }
    __syncthreads();

    // ---- Phase 3b: unified box means (r = 36 is fc) ----
    // Warp-uniform r, lanes = channels (stride 197 -> conflict-free).
    // top row for y1 == 0 is the broadcast zero row (conflict-free broadcast).
    for (int t = tid; t < (NBOX + 1) * 32; t += NTHREADS) {
        const int r = t >> 5;
        const int c = t & 31;
        const float* tp = tile + c * TS;
        const int x1 = bx1[r], x2 = bx2[r];
        const int y1 = by1[r], y2 = by2[r];
        const float* bot = tp + (y2 - 1) * PSZ + x1;
        const float* top = (y1 > 0) ? (tp + (y1 - 1) * PSZ + x1) : (zrow + x1 - (size_t)c * TS - x1);
        // NOTE: zrow branch must not include tp; fix pointer per-branch:
        if (y1 > 0) top = tp + (y1 - 1) * PSZ + x1; else top = zrow;
        const int w = x2 - x1;
        float s = 0.0f;
        #pragma unroll 4
        for (int x = 0; x < w; ++x) s += bot[x] - top[x];
        float* dst = (r < NBOX)
            ? (out + OFF_BU + ((size_t)b * NBOX + r) * CHAN + c0 + c)
            : (out + (size_t)b * CHAN + c0 + c);
        __stcs(dst, s * binv[r]);
    }
}

extern "C" void kernel_launch(void* const* d_in, const int* in_sizes, int n_in,
                              void* d_out, int out_size)
{
    const float* images = (const float*)d_in[0];
    const float* boxes  = (const float*)d_in[1];
    float* out = (float*)d_out;

    dim3 grid(CHAN / CT, BATCH);   // (64, 128) = 8192 blocks
    fused_pool_transpose_kernel<<<grid, NTHREADS>>>(images, boxes, out);
}

// round 12
// speedup vs baseline: 1.2676x; 1.1828x over previous
#include <cuda_runtime.h>
#include <cstdint>

// Problem constants (from reference setup_inputs)
#define BATCH 128
#define CHAN  2048
#define PSZ   14
#define HW    196              // 14*14
#define NBOX  36

#define CT      32             // channels per block tile
#define NTHREADS 256

// Output layout: fc [B,C] | att [B,HW,C] | bu [B,R,C]
#define OFF_ATT ((size_t)BATCH * CHAN)                          // 262144
#define OFF_BU  (OFF_ATT + (size_t)BATCH * HW * CHAN)           // 51642368
#define TILE_BYTES (CT * HW * 4)                                // 25088, mult of 16

__global__ __launch_bounds__(NTHREADS)
void fused_pool_transpose_tma(const float* __restrict__ images,
                              const float* __restrict__ boxes,
                              float* __restrict__ out)
{
    const int b   = blockIdx.y;
    const int c0  = blockIdx.x * CT;
    const int tid = threadIdx.x;

    // Linear tile (stride HW=196) — TMA writes it directly, no padding.
    __shared__ __align__(16) float tile[CT * HW];
    __shared__ int   bx1[NBOX + 1], by1[NBOX + 1], bx2[NBOX + 1], by2[NBOX + 1];
    __shared__ float binv[NBOX + 1];
    __shared__ __align__(8) unsigned long long mbar;

    const uint32_t mbar_a = (uint32_t)__cvta_generic_to_shared(&mbar);
    const uint32_t tile_a = (uint32_t)__cvta_generic_to_shared(tile);

    // ---- mbarrier init ----
    if (tid == 0)
        asm volatile("mbarrier.init.shared.b64 [%0], 1;" :: "r"(mbar_a) : "memory");
    __syncthreads();

    // ---- TMA bulk load: images[b, c0..c0+31, :] -> tile (25088B, 16B-aligned) ----
    if (tid == 0) {
        asm volatile("mbarrier.arrive.expect_tx.shared.b64 _, [%0], %1;"
                     :: "r"(mbar_a), "r"((uint32_t)TILE_BYTES) : "memory");
        const float* src = images + ((size_t)b * CHAN + c0) * HW;
        asm volatile(
            "cp.async.bulk.shared::cta.global.mbarrier::complete_tx::bytes "
            "[%0], [%1], %2, [%3];"
            :: "r"(tile_a), "l"(src), "r"((uint32_t)TILE_BYTES), "r"(mbar_a)
            : "memory");
    }

    // ---- Phase 0: box coords, overlapped with the TMA transfer ----
    if (tid <= NBOX) {
        int x1, y1, x2, y2;
        if (tid < NBOX) {
            const float* bp = boxes + ((size_t)b * NBOX + tid) * 4;
            x1 = (int)rintf(bp[0] * (float)PSZ);
            y1 = (int)rintf(bp[1] * (float)PSZ);
            x2 = (int)rintf(bp[2] * (float)PSZ);
            y2 = (int)rintf(bp[3] * (float)PSZ);
            // degenerate-box fix (matches reference exactly)
            if (x1 == x2) {
                if (x2 < PSZ)      x2 += 1;
                else if (x1 > 0)   x1 -= 1;
            }
            if (y1 == y2) {
                if (y2 < PSZ)      y2 += 1;
                else if (y1 > 0)   y1 -= 1;
            }
        } else {
            x1 = 0; y1 = 0; x2 = PSZ; y2 = PSZ;   // fc as full-plane box
        }
        bx1[tid] = x1; by1[tid] = y1; bx2[tid] = x2; by2[tid] = y2;
        binv[tid] = 1.0f / (float)((y2 - y1) * (x2 - x1));
    }

    // ---- Wait for TMA completion (phase parity 0; acquire per thread) ----
    {
        uint32_t done = 0;
        while (!done) {
            asm volatile(
                "{\n\t.reg .pred p;\n\t"
                "mbarrier.try_wait.parity.acquire.cta.shared::cta.b64 p, [%1], %2, 0x989680;\n\t"
                "selp.b32 %0, 1, 0, p;\n\t}"
                : "=r"(done) : "r"(mbar_a), "r"(0u) : "memory");
        }
    }

    // ---- Phase 2: att transpose ----
    // Per lane: LDS.128 of (channel = lane, positions 4q..4q+3).
    // LDS.128 runs in 8-lane phases; banks per phase = {4j+4q.. +3}, j=0..7
    // -> all 32 banks -> conflict-free. Stores: 4x scalar STG, each a full
    // 128B line (32 lanes = 32 consecutive channels at one position).
    {
        const int lane = tid & 31;
        const int wid  = tid >> 5;
        const float4* trow = reinterpret_cast<const float4*>(tile + lane * HW); // 784B rows, 16B aligned
        float* attb = out + OFF_ATT + (size_t)b * HW * CHAN + c0 + lane;
        for (int q = wid; q < HW / 4; q += 8) {        // 49 quads over 8 warps
            float4 v = trow[q];                        // positions 4q..4q+3
            float* o = attb + (size_t)(4 * q) * CHAN;
            __stcs(o,            v.x);
            __stcs(o + CHAN,     v.y);
            __stcs(o + 2 * CHAN, v.z);
            __stcs(o + 3 * CHAN, v.w);
        }
    }
    __syncthreads();

    // ---- Phase 3a: in-place y-prefix, diagonal column assignment ----
    // lane = channel c, column x = (x0 + (c>>3)) mod 14.
    // Banks = 4c + 14y + x ≡ 4j + k' + const (k' distinct per c>>3) -> conflict-free
    // (small 2-way residue only when the mod wraps). Each channel still sees
    // every column exactly once across the 14 x0 tasks.
    {
        const int c = tid & 31;
        const int k = c >> 3;
        float* tp = tile + c * HW;
        #pragma unroll
        for (int pass = 0; pass < 2; ++pass) {
            const int x0 = (tid >> 5) + pass * 8;
            if (x0 < PSZ) {
                int x = x0 + k; if (x >= PSZ) x -= PSZ;
                float* col = tp + x;
                float v[PSZ];
                #pragma unroll
                for (int y = 0; y < PSZ; ++y) v[y] = col[y * PSZ];
                #pragma unroll
                for (int y = 1; y < PSZ; ++y) v[y] += v[y - 1];
                #pragma unroll
                for (int y = 1; y < PSZ; ++y) col[y * PSZ] = v[y];
            }
        }
    }
    __syncthreads();

    // ---- Phase 3b: box means via y-prefix rows (r = 36 is fc) ----
    // Warp-uniform r, lane = channel. Rotated x-start per lane-quad breaks the
    // 4-way same-x bank conflict (banks 4j + (i + c>>3) pattern).
    for (int t = tid; t < (NBOX + 1) * 32; t += NTHREADS) {
        const int r = t >> 5;
        const int c = t & 31;
        const int k = c >> 3;
        const float* tp = tile + c * HW;
        const int x1 = bx1[r];
        const int w  = bx2[r] - x1;
        const int y1 = by1[r], y2 = by2[r];
        const float* bot = tp + (y2 - 1) * PSZ + x1;

        int idx = k;                       // rotate start by lane quad, mod w
        if (idx >= w) idx -= w;
        if (idx >= w) idx -= w;
        if (idx >= w) idx -= w;

        float s = 0.0f;
        if (y1 > 0) {
            const float* top = tp + (y1 - 1) * PSZ + x1;
            for (int i = 0; i < w; ++i) {
                s += bot[idx] - top[idx];
                ++idx; if (idx == w) idx = 0;
            }
        } else {
            for (int i = 0; i < w; ++i) {
                s += bot[idx];
                ++idx; if (idx == w) idx = 0;
            }
        }
        float* dst = (r < NBOX)
            ? (out + OFF_BU + ((size_t)b * NBOX + r) * CHAN + c0 + c)
            : (out + (size_t)b * CHAN + c0 + c);
        __stcs(dst, s * binv[r]);
    }
}

extern "C" void kernel_launch(void* const* d_in, const int* in_sizes, int n_in,
                              void* d_out, int out_size)
{
    const float* images = (const float*)d_in[0];
    const float* boxes  = (const float*)d_in[1];
    float* out = (float*)d_out;

    dim3 grid(CHAN / CT, BATCH);   // (64, 128) = 8192 blocks
    fused_pool_transpose_tma<<<grid, NTHREADS>>>(images, boxes, out);
}